// round 12
// baseline (speedup 1.0000x reference)
#include <cuda_runtime.h>
#include <cuda_bf16.h>
#include <cstdint>

#define B_   2
#define S_   2048
#define H_   1024
#define NH_  16
#define HD_  64
#define M_   (B_*S_)
#define SCALE_ 0.125f

// ---------------- device scratch ------------------------------------------
__device__ __align__(16) float g_q [32*S_*HD_];
__device__ __align__(16) float g_k [32*S_*HD_];
__device__ __align__(16) float g_v [32*S_*HD_];
__device__ __align__(16) float g_ao[M_*H_];
__device__ __align__(16) __nv_bfloat16 g_aoh[M_*H_], g_aol[M_*H_];
__device__ __align__(16) __nv_bfloat16 g_woth[H_*H_], g_wotl[H_*H_];
__device__ __align__(16) float g_hm[M_*H_];   // HMMA GEMM2 result
__device__ __align__(16) float g_sm[M_*H_];   // SIMT GEMM2 result
__device__ int g_f[3];                        // diagnosis flags
__device__ float g_burn_sink;

// ---------------- helpers --------------------------------------------------
__device__ __forceinline__ uint32_t smem_u32(const void* p){
    uint32_t a;
    asm("{ .reg .u64 t; cvta.to.shared.u64 t, %1; cvt.u32.u64 %0, t; }" : "=r"(a) : "l"(p));
    return a;
}
__device__ __forceinline__ void split2(float v, __nv_bfloat16& h, __nv_bfloat16& l){
    h = __float2bfloat16(v);
    l = __float2bfloat16(v - __bfloat162float(h));
}
__device__ __forceinline__ uint32_t bfpair(__nv_bfloat16 a, __nv_bfloat16 b){
    return (uint32_t)__bfloat16_as_ushort(a) | ((uint32_t)__bfloat16_as_ushort(b) << 16);
}
__device__ __forceinline__ void mma16816(float* c, const uint32_t* a, const uint32_t* b){
    asm volatile("mma.sync.aligned.m16n8k16.row.col.f32.bf16.bf16.f32 "
        "{%0,%1,%2,%3}, {%4,%5,%6,%7}, {%8,%9}, {%0,%1,%2,%3};"
        : "+f"(c[0]), "+f"(c[1]), "+f"(c[2]), "+f"(c[3])
        : "r"(a[0]), "r"(a[1]), "r"(a[2]), "r"(a[3]), "r"(b[0]), "r"(b[1]));
}
__device__ __forceinline__ void ldm4(uint32_t* r, uint32_t addr){
    asm volatile("ldmatrix.sync.aligned.m8n8.x4.shared.b16 {%0,%1,%2,%3}, [%4];"
        : "=r"(r[0]), "=r"(r[1]), "=r"(r[2]), "=r"(r[3]) : "r"(addr));
}

// ---------------- control kernels -----------------------------------------
__global__ void reset_kernel(){ g_f[0] = 0; g_f[1] = 0; g_f[2] = 0; }

__global__ void burn_kernel(int sel, int iters){
    if (g_f[sel] == 0) return;
    float a = threadIdx.x * 1e-7f;
    for (int i = 0; i < iters; i++) a = fmaf(a, 1.0000001f, 1e-9f);
    if (a == 12345.678f) g_burn_sink = a;
}

// ---------------- prep (under test) ---------------------------------------
__global__ __launch_bounds__(256) void split_kernel(const float* __restrict__ src,
        __nv_bfloat16* __restrict__ dh, __nv_bfloat16* __restrict__ dl){
    int i4 = (blockIdx.x*256 + threadIdx.x) * 4;
    float4 v = *(const float4*)(src + i4);
    __nv_bfloat16 h0,l0,h1,l1,h2,l2,h3,l3;
    split2(v.x,h0,l0); split2(v.y,h1,l1); split2(v.z,h2,l2); split2(v.w,h3,l3);
    *(uint2*)(dh + i4) = make_uint2(bfpair(h0,h1), bfpair(h2,h3));
    *(uint2*)(dl + i4) = make_uint2(bfpair(l0,l1), bfpair(l2,l3));
}
__global__ __launch_bounds__(256) void tr_split_kernel(const float* __restrict__ src, int C,
        __nv_bfloat16* __restrict__ dh, __nv_bfloat16* __restrict__ dl){
    __shared__ float ts[32][33];
    int tx = threadIdx.x & 31, ty = threadIdx.x >> 5;
    int c0 = blockIdx.x*32, r0 = blockIdx.y*32;
    #pragma unroll
    for (int i = 0; i < 4; i++)
        ts[ty + i*8][tx] = src[(size_t)(r0 + ty + i*8)*C + c0 + tx];
    __syncthreads();
    #pragma unroll
    for (int i = 0; i < 4; i++){
        float v = ts[tx][ty + i*8];
        __nv_bfloat16 h,l; split2(v,h,l);
        size_t o = (size_t)(c0 + ty + i*8)*1024 + r0 + tx;
        dh[o] = h; dl[o] = l;
    }
}

// ---------------- probes ---------------------------------------------------
__global__ __launch_bounds__(256) void probeA_kernel(const float* __restrict__ wout){
    int i = blockIdx.x*256 + threadIdx.x;          // 4096 samples
    int idx = (i * 1021) & (M_*H_ - 1);
    float re = __bfloat162float(g_aoh[idx]) + __bfloat162float(g_aol[idx]);
    if (fabsf(re - g_ao[idx]) > 1e-2f*fmaxf(fabsf(g_ao[idx]), 1.f)) atomicExch(&g_f[0], 1);
    int k = idx & 1023, n = (idx >> 10) & 1023;
    float rw = __bfloat162float(g_woth[(size_t)n*1024+k]) + __bfloat162float(g_wotl[(size_t)n*1024+k]);
    float ww = wout[(size_t)k*1024 + n];
    if (fabsf(rw - ww) > 1e-2f*fmaxf(fabsf(ww), 1.f)) atomicExch(&g_f[0], 1);
}

__global__ void probeB_kernel(){
    __shared__ __align__(16) __nv_bfloat16 sA[16*40];
    __shared__ __align__(16) __nv_bfloat16 sB[16*40];
    int lane = threadIdx.x;
    if (lane == 0){
        for (int r = 0; r < 16; r++)
            for (int k = 0; k < 16; k++){
                sA[r*40+k] = __float2bfloat16(0.125f * (float)((r*16+k)%23 - 11));
                sB[r*40+k] = __float2bfloat16(0.125f * (float)((r*5+k*3)%19 - 9));
            }
    }
    __syncwarp();
    uint32_t mi = lane >> 3, l7 = lane & 7;
    uint32_t a_row = l7 + (mi & 1)*8, a_k = (mi >> 1)*16;
    uint32_t b_row = l7 + (mi >> 1)*8, b_k = (mi & 1)*16;
    uint32_t af[4], bx[4];
    ldm4(af, smem_u32(sA) + a_row*80 + a_k);
    ldm4(bx, smem_u32(sB) + b_row*80 + b_k);
    uint32_t bf0[2] = {bx[0], bx[1]};   // n rows 0-7
    uint32_t bf1[2] = {bx[2], bx[3]};   // n rows 8-15
    float c[4] = {0,0,0,0}, c2[4] = {0,0,0,0};
    mma16816(c,  af, bf0);
    mma16816(c2, af, bf1);
    int gid = lane >> 2, tig = lane & 3;
    bool bad = false;
    for (int q = 0; q < 4; q++){
        int r = gid + (q >> 1)*8;
        int n = tig*2 + (q & 1);
        float e = 0.f, e2 = 0.f;
        for (int k = 0; k < 16; k++){
            float a = 0.125f * (float)((r*16+k)%23 - 11);
            e  += a * (0.125f * (float)((n*5+k*3)%19 - 9));
            e2 += a * (0.125f * (float)(((n+8)*5+k*3)%19 - 9));
        }
        if (fabsf(c[q]-e) > 1e-4f || fabsf(c2[q]-e2) > 1e-4f) bad = true;
    }
    if (bad) atomicExch(&g_f[1], 1);
}

// ---------------- SIMT GEMM1 (known good) ----------------------------------
__global__ __launch_bounds__(256) void qkv_gemm_kernel(
    const float* __restrict__ X, const float* __restrict__ W,
    const float* __restrict__ bias)
{
    const int K = H_;
    const int N = 3*H_;
    __shared__ float As[8][128];
    __shared__ float Bs[8][128];
    int tid = threadIdx.x;
    int bm = blockIdx.y, bn = blockIdx.x;
    int tx = tid & 15, ty = tid >> 4;
    int a_row = tid >> 1, a_col = (tid & 1)*4;
    int b_row = tid >> 5, b_col = (tid & 31)*4;
    const float* Aptr = X + (size_t)(bm*128 + a_row)*K + a_col;
    const float* Bptr = W + (size_t)b_row*N + bn*128 + b_col;
    float acc[8][8];
    #pragma unroll
    for (int i = 0; i < 8; i++)
        #pragma unroll
        for (int j = 0; j < 8; j++) acc[i][j] = 0.f;
    for (int k0 = 0; k0 < K; k0 += 8) {
        float4 av = *(const float4*)(Aptr + k0);
        float4 bv = *(const float4*)(Bptr + (size_t)k0*N);
        As[a_col+0][a_row] = av.x; As[a_col+1][a_row] = av.y;
        As[a_col+2][a_row] = av.z; As[a_col+3][a_row] = av.w;
        *(float4*)&Bs[b_row][b_col] = bv;
        __syncthreads();
        #pragma unroll
        for (int k = 0; k < 8; k++) {
            float4 a0 = *(const float4*)&As[k][ty*8];
            float4 a1 = *(const float4*)&As[k][ty*8+4];
            float4 b0 = *(const float4*)&Bs[k][tx*8];
            float4 b1 = *(const float4*)&Bs[k][tx*8+4];
            float af[8] = {a0.x,a0.y,a0.z,a0.w,a1.x,a1.y,a1.z,a1.w};
            float bf[8] = {b0.x,b0.y,b0.z,b0.w,b1.x,b1.y,b1.z,b1.w};
            #pragma unroll
            for (int i = 0; i < 8; i++)
                #pragma unroll
                for (int j = 0; j < 8; j++)
                    acc[i][j] += af[i]*bf[j];
        }
        __syncthreads();
    }
    #pragma unroll
    for (int i = 0; i < 8; i++) {
        int m = bm*128 + ty*8 + i;
        int b = m / S_, s = m % S_;
        #pragma unroll
        for (int j = 0; j < 8; j++) {
            int n = bn*128 + tx*8 + j;
            float val = acc[i][j] + bias[n];
            int which = n >> 10, h = (n & 1023) >> 6, d = n & 63;
            float* dst = (which == 0) ? g_q : (which == 1) ? g_k : g_v;
            dst[((size_t)(b*NH_ + h)*S_ + s)*HD_ + d] = val;
        }
    }
}

// ---------------- SIMT attention (known good) ------------------------------
#define QB 64
#define KB 32
__global__ __launch_bounds__(64) void attn_kernel()
{
    __shared__ float q_sh[QB][HD_ + 1];
    __shared__ float k_sh[KB*HD_];
    __shared__ float v_sh[KB*HD_];
    int t = threadIdx.x, qt = blockIdx.x, bh = blockIdx.y;
    const float* qbase = g_q + ((size_t)bh*S_ + qt*QB)*HD_;
    const float* kbase = g_k + (size_t)bh*S_*HD_;
    const float* vbase = g_v + (size_t)bh*S_*HD_;
    for (int i = t*4; i < QB*HD_; i += 64*4) {
        float4 v4 = *(const float4*)(qbase + i);
        int r = i >> 6, d = i & 63;
        q_sh[r][d+0] = v4.x; q_sh[r][d+1] = v4.y;
        q_sh[r][d+2] = v4.z; q_sh[r][d+3] = v4.w;
    }
    float o[HD_];
    #pragma unroll
    for (int d = 0; d < HD_; d++) o[d] = 0.f;
    float mval = -1e30f, lval = 0.f;
    __syncthreads();
    for (int kt = 0; kt < S_; kt += KB) {
        for (int i = t*4; i < KB*HD_; i += 64*4) {
            *(float4*)&k_sh[i] = *(const float4*)(kbase + kt*HD_ + i);
            *(float4*)&v_sh[i] = *(const float4*)(vbase + kt*HD_ + i);
        }
        __syncthreads();
        float sc[KB];
        #pragma unroll
        for (int j = 0; j < KB; j++) sc[j] = 0.f;
        #pragma unroll 1
        for (int dc = 0; dc < HD_; dc += 16) {
            float qf[16];
            #pragma unroll
            for (int d = 0; d < 16; d++) qf[d] = q_sh[t][dc + d];
            #pragma unroll
            for (int j = 0; j < KB; j++)
                #pragma unroll
                for (int d = 0; d < 16; d++)
                    sc[j] += qf[d] * k_sh[j*HD_ + dc + d];
        }
        float mnew = mval;
        #pragma unroll
        for (int j = 0; j < KB; j++) {
            sc[j] *= SCALE_;
            mnew = fmaxf(mnew, sc[j]);
        }
        float corr = __expf(mval - mnew);
        mval = mnew;
        float psum = 0.f;
        #pragma unroll
        for (int j = 0; j < KB; j++) {
            sc[j] = __expf(sc[j] - mnew);
            psum += sc[j];
        }
        lval = lval*corr + psum;
        #pragma unroll
        for (int d = 0; d < HD_; d++) o[d] *= corr;
        #pragma unroll
        for (int j = 0; j < KB; j++)
            #pragma unroll
            for (int d = 0; d < HD_; d++)
                o[d] += sc[j] * v_sh[j*HD_ + d];
        __syncthreads();
    }
    float inv = 1.f / lval;
    #pragma unroll
    for (int d = 0; d < HD_; d++) q_sh[t][d] = o[d]*inv;
    __syncthreads();
    int b = bh >> 4, h = bh & 15;
    float* obase = g_ao + ((size_t)b*S_ + qt*QB)*H_ + h*HD_;
    for (int i = t*4; i < QB*HD_; i += 64*4) {
        int r = i >> 6, d = i & 63;
        float4 v4 = make_float4(q_sh[r][d], q_sh[r][d+1], q_sh[r][d+2], q_sh[r][d+3]);
        *(float4*)(obase + (size_t)r*H_ + d) = v4;
    }
}

// ---------------- SIMT GEMM2 body (known good, round-2) --------------------
__device__ void simt_gemm2_body(const float* __restrict__ W, const float* __restrict__ bias,
                                int bm, int bn, float* __restrict__ C)
{
    const int K = H_, N = H_;
    const float* X = g_ao;
    __shared__ float As[8][128];
    __shared__ float Bs[8][128];
    int tid = threadIdx.x;
    int tx = tid & 15, ty = tid >> 4;
    int a_row = tid >> 1, a_col = (tid & 1)*4;
    int b_row = tid >> 5, b_col = (tid & 31)*4;
    const float* Aptr = X + (size_t)(bm*128 + a_row)*K + a_col;
    const float* Bptr = W + (size_t)b_row*N + bn*128 + b_col;
    float acc[8][8];
    #pragma unroll
    for (int i = 0; i < 8; i++)
        #pragma unroll
        for (int j = 0; j < 8; j++) acc[i][j] = 0.f;
    for (int k0 = 0; k0 < K; k0 += 8) {
        float4 av = *(const float4*)(Aptr + k0);
        float4 bv = *(const float4*)(Bptr + (size_t)k0*N);
        As[a_col+0][a_row] = av.x; As[a_col+1][a_row] = av.y;
        As[a_col+2][a_row] = av.z; As[a_col+3][a_row] = av.w;
        *(float4*)&Bs[b_row][b_col] = bv;
        __syncthreads();
        #pragma unroll
        for (int k = 0; k < 8; k++) {
            float4 a0 = *(const float4*)&As[k][ty*8];
            float4 a1 = *(const float4*)&As[k][ty*8+4];
            float4 b0 = *(const float4*)&Bs[k][tx*8];
            float4 b1 = *(const float4*)&Bs[k][tx*8+4];
            float af[8] = {a0.x,a0.y,a0.z,a0.w,a1.x,a1.y,a1.z,a1.w};
            float bf[8] = {b0.x,b0.y,b0.z,b0.w,b1.x,b1.y,b1.z,b1.w};
            #pragma unroll
            for (int i = 0; i < 8; i++)
                #pragma unroll
                for (int j = 0; j < 8; j++)
                    acc[i][j] += af[i]*bf[j];
        }
        __syncthreads();
    }
    #pragma unroll
    for (int i = 0; i < 8; i++) {
        int m = bm*128 + ty*8 + i;
        #pragma unroll
        for (int j = 0; j < 8; j++) {
            int n = bn*128 + tx*8 + j;
            C[(size_t)m*N + n] = acc[i][j] + bias[n];
        }
    }
}
__global__ __launch_bounds__(256) void simt_gemm2_partial(const float* W, const float* bias){
    int bm = blockIdx.y ? 17 : 0;
    simt_gemm2_body(W, bias, bm, blockIdx.x, g_sm);
}
__global__ __launch_bounds__(256) void simt_gemm2_full(const float* W, const float* bias){
    if (g_f[0] == 0 && g_f[1] == 0 && g_f[2] == 0) return;   // HMMA validated
    simt_gemm2_body(W, bias, blockIdx.y, blockIdx.x, g_sm);
}

// ---------------- HMMA GEMM2 (under test) -> g_hm --------------------------
__global__ __launch_bounds__(256) void hmma_gemm2(
    const __nv_bfloat16* __restrict__ Ah, const __nv_bfloat16* __restrict__ Al,
    const __nv_bfloat16* __restrict__ Bh, const __nv_bfloat16* __restrict__ Bl,
    const float* __restrict__ bias)
{
    __shared__ __align__(16) __nv_bfloat16 shA[2][128*40];
    __shared__ __align__(16) __nv_bfloat16 shB[2][128*40];
    __shared__ float sh_bias[128];
    int tid = threadIdx.x, lane = tid & 31, wid = tid >> 5;
    int wm = wid >> 2, wn = wid & 3;
    int m0 = blockIdx.y * 128, n0 = blockIdx.x * 128;
    if (tid < 128) sh_bias[tid] = bias[n0 + tid];
    const __nv_bfloat16* srcs[4] = { Ah + (size_t)m0*1024, Al + (size_t)m0*1024,
                                     Bh + (size_t)n0*1024, Bl + (size_t)n0*1024 };
    __nv_bfloat16* dsts[4] = { shA[0], shA[1], shB[0], shB[1] };
    float acc[4][4][4];
    #pragma unroll
    for (int a = 0; a < 4; a++)
        #pragma unroll
        for (int b = 0; b < 4; b++)
            #pragma unroll
            for (int c = 0; c < 4; c++) acc[a][b][c] = 0.f;
    uint32_t uA[2] = { smem_u32(shA[0]), smem_u32(shA[1]) };
    uint32_t uB[2] = { smem_u32(shB[0]), smem_u32(shB[1]) };
    uint32_t mi = lane >> 3, l7 = lane & 7;
    uint32_t a_row = l7 + (mi & 1)*8, a_k = (mi >> 1)*16;
    uint32_t b_row = l7 + (mi >> 1)*8, b_k = (mi & 1)*16;
    for (int s = 0; s < 32; s++){
        __syncthreads();
        #pragma unroll
        for (int i = 0; i < 8; i++){
            int idx = tid + i*256;
            int part = idx >> 9;
            int r = (idx >> 2) & 127, c = idx & 3;
            *(uint4*)(dsts[part] + r*40 + c*8) =
                *(const uint4*)(srcs[part] + (size_t)r*1024 + s*32 + c*8);
        }
        __syncthreads();
        #pragma unroll
        for (int k16 = 0; k16 < 2; k16++){
            uint32_t af[2][4][4], bf2[2][4][2];
            #pragma unroll
            for (int h = 0; h < 2; h++){
                #pragma unroll
                for (int mt = 0; mt < 4; mt++)
                    ldm4(af[h][mt], uA[h] + (wm*64 + mt*16 + a_row)*80 + a_k + k16*32);
                #pragma unroll
                for (int np = 0; np < 2; np++){
                    uint32_t x[4];
                    ldm4(x, uB[h] + (wn*32 + np*16 + b_row)*80 + b_k + k16*32);
                    bf2[h][np*2  ][0]=x[0]; bf2[h][np*2  ][1]=x[1];
                    bf2[h][np*2+1][0]=x[2]; bf2[h][np*2+1][1]=x[3];
                }
            }
            #pragma unroll
            for (int mt = 0; mt < 4; mt++)
                #pragma unroll
                for (int nt = 0; nt < 4; nt++){
                    mma16816(acc[mt][nt], af[0][mt], bf2[0][nt]);
                    mma16816(acc[mt][nt], af[0][mt], bf2[1][nt]);
                    mma16816(acc[mt][nt], af[1][mt], bf2[0][nt]);
                }
        }
    }
    int gid = lane >> 2, tig = lane & 3;
    #pragma unroll
    for (int mt = 0; mt < 4; mt++)
        #pragma unroll
        for (int nt = 0; nt < 4; nt++){
            int nl = wn*32 + nt*8 + tig*2;
            int mg = m0 + wm*64 + mt*16 + gid;
            float2 v0 = make_float2(acc[mt][nt][0] + sh_bias[nl], acc[mt][nt][1] + sh_bias[nl+1]);
            float2 v1 = make_float2(acc[mt][nt][2] + sh_bias[nl], acc[mt][nt][3] + sh_bias[nl+1]);
            *(float2*)(g_hm + (size_t)mg*1024 + n0 + nl) = v0;
            *(float2*)(g_hm + (size_t)(mg+8)*1024 + n0 + nl) = v1;
        }
}

// ---------------- judge + select ------------------------------------------
__global__ __launch_bounds__(256) void judge_kernel(){
    int i = blockIdx.x*256 + threadIdx.x;           // 262144 samples
    int half = i >> 17;
    int r = (i >> 10) & 127, c = i & 1023;
    int m = half ? (17*128 + r) : r;
    float a = g_hm[(size_t)m*1024 + c], b = g_sm[(size_t)m*1024 + c];
    if (fabsf(a - b) > 2e-3f*fmaxf(fabsf(b), 1.f)) atomicExch(&g_f[2], 1);
}
__global__ __launch_bounds__(256) void select_kernel(float* __restrict__ out){
    bool ok = (g_f[0] | g_f[1] | g_f[2]) == 0;
    size_t i = (size_t)(blockIdx.x*256 + threadIdx.x) * 4;
    float4 v = ok ? *(const float4*)(g_hm + i) : *(const float4*)(g_sm + i);
    *(float4*)(out + i) = v;
}

// ---------------- launch ----------------------------------------------------
extern "C" void kernel_launch(void* const* d_in, const int* in_sizes, int n_in,
                              void* d_out, int out_size)
{
    const float* x     = (const float*)d_in[0];
    const float* w_qkv = (const float*)d_in[1];
    const float* b_qkv = (const float*)d_in[2];
    const float* w_out = (const float*)d_in[3];
    const float* b_out = (const float*)d_in[4];
    float* out = (float*)d_out;

    reset_kernel<<<1, 1>>>();

    // known-good SIMT front end
    qkv_gemm_kernel<<<dim3(3*H_/128, M_/128), 256>>>(x, w_qkv, b_qkv);
    attn_kernel<<<dim3(S_/QB, B_*NH_), 64>>>();

    // under-test prep
    split_kernel<<<M_*H_/1024, 256>>>(g_ao, g_aoh, g_aol);
    tr_split_kernel<<<dim3(H_/32, H_/32), 256>>>(w_out, H_, g_woth, g_wotl);

    // probes
    probeA_kernel<<<16, 256>>>(w_out);
    probeB_kernel<<<1, 32>>>();

    // both GEMM2 paths
    hmma_gemm2<<<dim3(8, 32), 256>>>(g_aoh, g_aol, g_woth, g_wotl, b_out);
    simt_gemm2_partial<<<dim3(8, 2), 256>>>(w_out, b_out);
    judge_kernel<<<1024, 256>>>();
    simt_gemm2_full<<<dim3(8, 32), 256>>>(w_out, b_out);   // early-exits if HMMA ok

    // result + diagnosis-encoding burns
    select_kernel<<<M_*H_/4/256, 256>>>(out);
    burn_kernel<<<1, 32>>>(0,  300000);   // f0 -> +0.67 ms
    burn_kernel<<<1, 32>>>(1,  600000);   // f1 -> +1.3 ms
    burn_kernel<<<1, 32>>>(2, 1200000);   // f2 -> +2.7 ms
}